// round 15
// baseline (speedup 1.0000x reference)
#include <cuda_runtime.h>
#include <math.h>

#define HW   (128*128)
#define CHW  (16*HW)
#define WSTG (9*3*2304)      // merged-weight floats per stage
typedef unsigned long long ull;

// ---------------- scratch ----------------
__device__ float g_b1[7*CHW];    // conv1 out (3) / conv3 out (7)
__device__ float g_b2[5*CHW];    // conv2 out (5) -- kept for final skip recompute
__device__ float g_b3[9*CHW];    // conv4 out (9)
__device__ float g_wm[4*WSTG];   // pre-merged weights [stage][osl][e][ci*144+k*16+co]
__device__ float g_sum[4*16];
__device__ float g_sumsq[4*16];

struct Taps { int isl[9][3]; int msk[9][3]; float mult[9]; };
struct MergeArgs { const float* w[4]; Taps tp[4]; int n_osl[4]; };

// ---------------- f32x2 helpers ----------------
__device__ __forceinline__ ull pack2(float v){
    ull r; asm("mov.b64 %0,{%1,%2};" : "=l"(r) : "f"(v), "f"(v)); return r;
}
__device__ __forceinline__ void fma2(ull &d, ull a, ull b){
    asm("fma.rn.f32x2 %0,%1,%2,%0;" : "+l"(d) : "l"(a), "l"(b));
}
__device__ __forceinline__ void unpack2(ull a, float &x, float &y){
    asm("mov.b64 {%0,%1},%2;" : "=f"(x), "=f"(y) : "l"(a));
}

// ---------------- setup: merge weights (once) + zero stats ----------------
__global__ __launch_bounds__(128) void merge_weights(MergeArgs a)
{
    const int e = blockIdx.x, osl = blockIdx.y, st = blockIdx.z;
    const int tid = threadIdx.x;
    if (e==0 && osl==0 && st==0 && tid < 64){ g_sum[tid]=0.f; g_sumsq[tid]=0.f; }
    if (osl >= a.n_osl[st]) return;
    const int isl = a.tp[st].isl[osl][e];
    if (isl < 0) return;
    const int m = a.tp[st].msk[osl][e];
    const float* w = a.w[st];
    float* dst = g_wm + st*WSTG + (osl*3 + e)*2304;
#pragma unroll
    for (int it=0; it<18; it++){
        int idx = tid + it*128;
        int co = idx & 15;
        int k  = (idx >> 4) % 9;
        int ci = idx / 144;
        int base = ((co*16+ci)*9 + k)*3;
        float wv = 0.f;
        if (m & 1) wv += w[base+0];
        if (m & 2) wv += w[base+1];
        if (m & 4) wv += w[base+2];
        dst[idx] = wv;
    }
}

// ---------------- fused conv stage ----------------
// MODE 0: raw input. MODE 1: relu(fma(x,a,b)), a=istd, b=-mean*istd finalized
// inline from raw atomic sums. MODE 2: relu(fma(x,a,b) + skip).
// Halo: transform only in-range pixels; out-of-range pad = 0.
// Block: 128 threads = 32 strips x 4 co-groups. Thread = 1x8 px strip x 4 co
// (16 f32x2 accs). Input tile stored as DUPLICATED f32x2 pairs {v,v} so the
// compute loop has ZERO pack MOVs: values load directly as ull2 operands.
// Tile 8z x 32y; grid x = 64 tiles, y = output slice. R12 config otherwise.
template<int MODE>
__global__ __launch_bounds__(128, 4) void conv_stage(
    const float* __restrict__ in, size_t in_stride,
    float* __restrict__ out,
    const float* __restrict__ wm, const float* __restrict__ bias,
    const float* __restrict__ prev_s, const float* __restrict__ prev_q,
    const float* __restrict__ skip,
    float* __restrict__ stat_s, float* __restrict__ stat_q,
    Taps tp)
{
    __shared__ __align__(16) float s_w[16*9*16];   // [ci][k][co]
    __shared__ __align__(16) ull   s_in[16*360];   // [ci][r(10)][c(36, 34 used)] dup pairs
    __shared__ float s_a[16], s_b[16];
    __shared__ float s_red[4][4][8];    // [warp][cg][4 s + 4 q]

    const int osl = blockIdx.y;
    const int tile = blockIdx.x;
    const int tz0 = (tile >> 2) << 3;   // 16 z-tiles of 8
    const int ty0 = (tile &  3) << 5;   // 4 y-tiles of 32
    const int tid = threadIdx.x;
    const int cg    = tid & 3;          // co-group: co = cg*4 .. cg*4+3
    const int slot  = tid >> 2;         // 0..31
    const int tz    = slot >> 2;        // 0..7
    const int strip = slot & 3;         // 0..3 -> y = strip*8 .. strip*8+7

    // inline finalize of previous stage's instance-norm stats
    if (MODE > 0 && tid < 16){
        double sd = (double)prev_s[tid];
        double qd = (double)prev_q[tid];
        double mean = sd / 2097152.0;
        double var  = qd / 2097152.0 - mean*mean;
        double isd  = 1.0 / sqrt(var + 1e-5);
        s_a[tid] = (float)isd;
        s_b[tid] = (float)(-mean*isd);
    }

    // tile-load slots over 340 logical entries (r=j/34, c=j%34):
    // slots 0,1 for all threads; slot 2 only for tid<84 (340-256).
    int pxs[3], sos[3]; bool oks[3];
#pragma unroll
    for (int s3=0; s3<3; s3++){
        int j = tid + s3*128;
        int r = j/34, c = j - r*34;
        int gz = tz0 + r - 1, gy = ty0 + c - 1;
        oks[s3] = (j < 340) && ((unsigned)gz < 128u) && ((unsigned)gy < 128u);
        pxs[s3] = gz*128 + gy;
        sos[s3] = r*36 + c;
    }
    const bool has2 = tid < 84;

    ull acc[2][8];                      // [co-pair][py]
#pragma unroll
    for (int p=0;p<2;p++)
#pragma unroll
    for (int py=0;py<8;py++) acc[p][py] = 0ull;

    for (int e=0; e<3; e++){
        const int isl = tp.isl[osl][e];
        if (isl < 0) continue;
        __syncthreads();
        // weights: coalesced copy of pre-merged slab (576 float4)
        {
            const float4* wmp = reinterpret_cast<const float4*>(wm + (osl*3 + e)*2304);
            float4* swp = reinterpret_cast<float4*>(s_w);
#pragma unroll
            for (int it=0; it<4; it++)
                swp[tid + it*128] = wmp[tid + it*128];
            if (tid < 64) swp[tid + 512] = wmp[tid + 512];
        }
        // input tile: ci batched in groups of 4, 3 slots per thread;
        // store duplicated pairs {v,v}
        const float* ip = in + (size_t)isl*in_stride;
#pragma unroll
        for (int s3=0; s3<3; s3++){
            if (s3==2 && !has2) break;
            const bool ok = oks[s3];
            const int px = pxs[s3], so = sos[s3];
#pragma unroll
            for (int cgl=0; cgl<16; cgl+=4){
                float xv[4];
#pragma unroll
                for (int u2=0; u2<4; u2++)
                    xv[u2] = ok ? ip[(cgl+u2)*HW + px] : 0.f;
                if (MODE == 2){
                    float svv[4];
#pragma unroll
                    for (int u2=0; u2<4; u2++)
                        svv[u2] = ok ? skip[(cgl+u2)*HW + px] : 0.f;
#pragma unroll
                    for (int u2=0; u2<4; u2++){
                        float t = fmaxf(fmaf(xv[u2], s_a[cgl+u2], s_b[cgl+u2]) + svv[u2], 0.f);
                        s_in[(cgl+u2)*360 + so] = ok ? pack2(t) : 0ull;
                    }
                } else if (MODE == 1){
#pragma unroll
                    for (int u2=0; u2<4; u2++){
                        float t = fmaxf(fmaf(xv[u2], s_a[cgl+u2], s_b[cgl+u2]), 0.f);
                        s_in[(cgl+u2)*360 + so] = ok ? pack2(t) : 0ull;
                    }
                } else {
#pragma unroll
                    for (int u2=0; u2<4; u2++)
                        s_in[(cgl+u2)*360 + so] = ok ? pack2(xv[u2]) : 0ull;
                }
            }
        }
        __syncthreads();

        // compute: 8 px x 4 co; values pre-duplicated -> zero MOVs
        const ull* sbase = s_in + tz*36 + strip*8;
        const float* wb  = s_w  + cg*4;
#pragma unroll 2
        for (int ci=0; ci<16; ci++){
            const ull*   si    = sbase + ci*360;
            const float* wbase = wb    + ci*144;
#pragma unroll
            for (int kz=0; kz<3; kz++){
                const ulonglong2* rp = reinterpret_cast<const ulonglong2*>(si + kz*36);
                ull pv[10];
#pragma unroll
                for (int j=0;j<5;j++){
                    ulonglong2 t2 = rp[j];
                    pv[2*j]=t2.x; pv[2*j+1]=t2.y;
                }
#pragma unroll
                for (int ky=0; ky<3; ky++){
                    ulonglong2 wq = *reinterpret_cast<const ulonglong2*>(wbase + (kz*3+ky)*16);
#pragma unroll
                    for (int py=0; py<8; py++){
                        fma2(acc[0][py], pv[ky+py], wq.x);
                        fma2(acc[1][py], pv[ky+py], wq.y);
                    }
                }
            }
        }
    }

    // epilogue: bias, vectorized store, fused stats
    const int oz  = tz0 + tz;
    const int oy0 = ty0 + strip*8;
    float* op = out + (size_t)osl*CHW + oz*128 + oy0;

    float sv[4], qv[4];
#pragma unroll
    for (int p=0; p<2; p++){
        const int c0 = cg*4 + 2*p, c1 = c0 + 1;
        const float b0 = bias[c0], b1 = bias[c1];
        float r0[8], r1[8];
#pragma unroll
        for (int py=0; py<8; py++){
            float x,y; unpack2(acc[p][py], x, y);
            r0[py] = x + b0;
            r1[py] = y + b1;
        }
        *reinterpret_cast<float4*>(op + c0*HW)     = make_float4(r0[0],r0[1],r0[2],r0[3]);
        *reinterpret_cast<float4*>(op + c0*HW + 4) = make_float4(r0[4],r0[5],r0[6],r0[7]);
        *reinterpret_cast<float4*>(op + c1*HW)     = make_float4(r1[0],r1[1],r1[2],r1[3]);
        *reinterpret_cast<float4*>(op + c1*HW + 4) = make_float4(r1[4],r1[5],r1[6],r1[7]);
        float s0=0.f,q0=0.f,s1=0.f,q1=0.f;
#pragma unroll
        for (int py=0; py<8; py++){
            s0 += r0[py]; q0 += r0[py]*r0[py];
            s1 += r1[py]; q1 += r1[py]*r1[py];
        }
        sv[2*p]=s0; qv[2*p]=q0; sv[2*p+1]=s1; qv[2*p+1]=q1;
    }
    // reduce over the 8 slots in this warp (lane bits 2..4)
#pragma unroll
    for (int o=16; o>=4; o>>=1){
#pragma unroll
        for (int j=0;j<4;j++){
            sv[j] += __shfl_xor_sync(0xffffffffu, sv[j], o);
            qv[j] += __shfl_xor_sync(0xffffffffu, qv[j], o);
        }
    }
    if ((tid & 31) < 4){
        const int wd = tid >> 5;
#pragma unroll
        for (int j=0;j<4;j++){
            s_red[wd][cg][j]   = sv[j];
            s_red[wd][cg][4+j] = qv[j];
        }
    }
    __syncthreads();
    if (tid < 32){
        const bool isq = tid >= 16;
        const int co = tid & 15;
        const int cgg = co >> 2, j = co & 3;
        const int off = isq ? (4+j) : j;
        float t = s_red[0][cgg][off] + s_red[1][cgg][off]
                + s_red[2][cgg][off] + s_red[3][cgg][off];
        t *= tp.mult[osl];
        atomicAdd(isq ? &stat_q[co] : &stat_s[co], t);
    }
}

// ---------------- fused final elementwise + forward projection ----------------
// final[sl] = relu( norm3(s3[sl]) + relu( norm1(s2[skm[sl]]) + V ) )
// out[c,0,z,u] = weighted slice sum at (z,y=u)
// out[c,1,z,u] = column sum over y of slice sel(u); u==0 sums only y=0..63
//   (reference fp32: x=+-3.9e-15 at uu=0, valid mask kills y in [64,127]).
__global__ __launch_bounds__(128) void forward_proj(
    const float* __restrict__ s3, const float* __restrict__ s2,
    const float* __restrict__ V, float* __restrict__ out)
{
    __shared__ float red[9][4];
    __shared__ float rs[9];
    const int c = blockIdx.x >> 7, z = blockIdx.x & 127;
    const int u = threadIdx.x;
    const int   skm[9]  = {0,1,2,2,2,2,2,3,4};
    const float mult[9] = {1.f,1.f,1.f,1.f,120.f,1.f,1.f,1.f,1.f};

    // inline stats finalize: bank1 (A2 output) and bank3 (B2 output)
    double sd1 = (double)g_sum[16+c], qd1 = (double)g_sumsq[16+c];
    double me1 = sd1/2097152.0;
    double i1d = 1.0/sqrt(qd1/2097152.0 - me1*me1 + 1e-5);
    const float i1 = (float)i1d, b1c = (float)(-me1*i1d);
    double sd3 = (double)g_sum[48+c], qd3 = (double)g_sumsq[48+c];
    double me3 = sd3/2097152.0;
    double i3d = 1.0/sqrt(qd3/2097152.0 - me3*me3 + 1e-5);
    const float i3 = (float)i3d, b3c = (float)(-me3*i3d);

    const int pix = z*128 + u;
    const float vb = V[c*HW + pix];

    float vals[9]; float s0 = 0.f;
#pragma unroll
    for (int sdx=0; sdx<9; sdx++){
        float t2 = s2[(size_t)(skm[sdx]*16 + c)*HW + pix];
        float sk = fmaxf(fmaf(t2, i1, b1c) + vb, 0.f);
        float t3 = s3[(size_t)(sdx*16 + c)*HW + pix];
        float fv = fmaxf(fmaf(t3, i3, b3c) + sk, 0.f);
        vals[sdx] = fv;
        s0 += mult[sdx]*fv;
    }
    out[(c*2+0)*HW + pix] = s0;

    const int lane = u & 31, wid = u >> 5;
#pragma unroll
    for (int sdx=0; sdx<9; sdx++){
        float v = vals[sdx];
#pragma unroll
        for (int o=16;o>0;o>>=1) v += __shfl_xor_sync(0xffffffffu, v, o);
        if (lane==0) red[sdx][wid]=v;
    }
    __syncthreads();
    if (u < 9) rs[u] = red[u][0]+red[u][1]+red[u][2]+red[u][3];
    __syncthreads();
    const int sl = (u<4) ? u : (u>123 ? u-119 : 4);
    float o1 = (u==0) ? (red[0][0]+red[0][1]) : rs[sl];
    out[(c*2+1)*HW + pix] = o1;
}

// ---------------- launch ----------------
extern "C" void kernel_launch(void* const* d_in, const int* in_sizes, int n_in,
                              void* d_out, int out_size)
{
    (void)in_sizes; (void)n_in; (void)out_size;
    const float* V    = (const float*)d_in[0];
    const float* w_a1 = (const float*)d_in[1];
    const float* b_a1 = (const float*)d_in[2];
    const float* w_a2 = (const float*)d_in[3];
    const float* b_a2 = (const float*)d_in[4];
    const float* w_b1 = (const float*)d_in[5];
    const float* b_b1 = (const float*)d_in[6];
    const float* w_b2 = (const float*)d_in[7];
    const float* b_b2 = (const float*)d_in[8];
    float* out = (float*)d_out;

    float *b1,*b2,*b3,*gsum,*gsq,*gwm;
    cudaGetSymbolAddress((void**)&b1,    g_b1);
    cudaGetSymbolAddress((void**)&b2,    g_b2);
    cudaGetSymbolAddress((void**)&b3,    g_b3);
    cudaGetSymbolAddress((void**)&gsum,  g_sum);
    cudaGetSymbolAddress((void**)&gsq,   g_sumsq);
    cudaGetSymbolAddress((void**)&gwm,   g_wm);

    // merged tap tables: (input slice, kx bitmask) per output slice
    Taps tA1 = {
        { {0,-1,-1},{0,-1,-1},{0,-1,-1} },
        { {6,0,0},{7,0,0},{3,0,0} },
        { 1.f,126.f,1.f }
    };
    Taps tA2 = {
        { {0,1,-1},{0,1,-1},{1,-1,-1},{1,2,-1},{1,2,-1} },
        { {2,4,0},{1,6,0},{7,0,0},{3,4,0},{1,2,0} },
        { 1.f,1.f,124.f,1.f,1.f }
    };
    Taps tB1 = {
        { {0,1,-1},{0,1,2},{1,2,-1},{2,-1,-1},{2,3,-1},{2,3,4},{3,4,-1} },
        { {2,4,0},{1,2,4},{1,6,0},{7,0,0},{3,4,0},{1,2,4},{1,2,0} },
        { 1.f,1.f,1.f,122.f,1.f,1.f,1.f }
    };
    Taps tB2 = {
        { {0,1,-1},{0,1,2},{1,2,3},{2,3,-1},{3,-1,-1},{3,4,-1},{3,4,5},{4,5,6},{5,6,-1} },
        { {2,4,0},{1,2,4},{1,2,4},{1,6,0},{7,0,0},{3,4,0},{1,2,4},{1,2,4},{1,2,0} },
        { 1.f,1.f,1.f,1.f,120.f,1.f,1.f,1.f,1.f }
    };

    MergeArgs ma;
    ma.w[0]=w_a1; ma.w[1]=w_a2; ma.w[2]=w_b1; ma.w[3]=w_b2;
    ma.tp[0]=tA1; ma.tp[1]=tA2; ma.tp[2]=tB1; ma.tp[3]=tB2;
    ma.n_osl[0]=3; ma.n_osl[1]=5; ma.n_osl[2]=7; ma.n_osl[3]=9;

    // setup: merge weights for all 4 stages + zero stats
    merge_weights<<<dim3(3,9,4),128>>>(ma);

    // A1: raw V (slice stride 0) -> b1 (3 slices), stats bank 0
    conv_stage<0><<<dim3(64,3),128>>>(V, 0, b1, gwm+0*WSTG, b_a1,
                                      nullptr, nullptr, nullptr,
                                      gsum+0, gsq+0, tA1);

    // A2: norm_relu(b1, bank0) -> b2 (5), stats bank 1
    conv_stage<1><<<dim3(64,5),128>>>(b1, CHW, b2, gwm+1*WSTG, b_a2,
                                      gsum+0, gsq+0, nullptr,
                                      gsum+16, gsq+16, tA2);

    // B1: relu(norm(b2, bank1) + V) -> b1 (7), stats bank 2
    conv_stage<2><<<dim3(64,7),128>>>(b2, CHW, b1, gwm+2*WSTG, b_b1,
                                      gsum+16, gsq+16, V,
                                      gsum+32, gsq+32, tB1);

    // B2: norm_relu(b1, bank2) -> b3 (9), stats bank 3
    conv_stage<1><<<dim3(64,9),128>>>(b1, CHW, b3, gwm+3*WSTG, b_b2,
                                      gsum+32, gsq+32, nullptr,
                                      gsum+48, gsq+48, tB2);

    // fused final norm+skip+relu + both projections (bank1+bank3 inline)
    forward_proj<<<16*128,128>>>(b3, b2, V, out);
}

// round 16
// speedup vs baseline: 1.1175x; 1.1175x over previous
#include <cuda_runtime.h>
#include <math.h>

#define HW   (128*128)
#define CHW  (16*HW)
#define WSTG (9*3*2304)      // merged-weight floats per stage
typedef unsigned long long ull;

// ---------------- scratch ----------------
__device__ float g_b1[7*CHW];    // conv1 out (3) / conv3 out (7)
__device__ float g_b2[5*CHW];    // conv2 out (5) -- kept for final skip recompute
__device__ float g_b3[9*CHW];    // conv4 out (9)
__device__ float g_wm[4*WSTG];   // pre-merged weights [stage][osl][e][ci*144+k*16+co]
__device__ float g_sum[4*16];
__device__ float g_sumsq[4*16];

struct Taps { int isl[9][3]; int msk[9][3]; float mult[9]; };
struct MergeArgs { const float* w[4]; Taps tp[4]; int n_osl[4]; };

// ---------------- f32x2 helpers ----------------
__device__ __forceinline__ ull pack2(float v){
    ull r; asm("mov.b64 %0,{%1,%2};" : "=l"(r) : "f"(v), "f"(v)); return r;
}
__device__ __forceinline__ void fma2(ull &d, ull a, ull b){
    asm("fma.rn.f32x2 %0,%1,%2,%0;" : "+l"(d) : "l"(a), "l"(b));
}
__device__ __forceinline__ void unpack2(ull a, float &x, float &y){
    asm("mov.b64 {%0,%1},%2;" : "=f"(x), "=f"(y) : "l"(a));
}

// ---------------- setup: merge weights (once) + zero stats ----------------
__global__ __launch_bounds__(128) void merge_weights(MergeArgs a)
{
    const int e = blockIdx.x, osl = blockIdx.y, st = blockIdx.z;
    const int tid = threadIdx.x;
    if (e==0 && osl==0 && st==0 && tid < 64){ g_sum[tid]=0.f; g_sumsq[tid]=0.f; }
    if (osl >= a.n_osl[st]) return;
    const int isl = a.tp[st].isl[osl][e];
    if (isl < 0) return;
    const int m = a.tp[st].msk[osl][e];
    const float* w = a.w[st];
    float* dst = g_wm + st*WSTG + (osl*3 + e)*2304;
#pragma unroll
    for (int it=0; it<18; it++){
        int idx = tid + it*128;
        int co = idx & 15;
        int k  = (idx >> 4) % 9;
        int ci = idx / 144;
        int base = ((co*16+ci)*9 + k)*3;
        float wv = 0.f;
        if (m & 1) wv += w[base+0];
        if (m & 2) wv += w[base+1];
        if (m & 4) wv += w[base+2];
        dst[idx] = wv;
    }
}

// ---------------- fused conv stage ----------------
// MODE 0: raw input. MODE 1: relu(fma(x,a,b)), a=istd, b=-mean*istd finalized
// inline from raw atomic sums. MODE 2: relu(fma(x,a,b) + skip).
// Halo: transform only in-range pixels; out-of-range pad = 0.
// Block: 128 threads = 32 strips x 4 co-groups. Thread = 1x8 px strip x 4 co
// (16 f32x2 accs). Tile 8z x 32y; grid x = 64 tiles, y = output slice.
// Compute loop is software-pipelined: next (ci,kz) row's value+weight LDS
// issue during current row's 48 FFMA2 (hides the 29-cyc LDS latency at
// ~3 warps/SMSP occupancy). Weight pointer advances linearly +48 floats/row.
template<int MODE>
__global__ __launch_bounds__(128, 4) void conv_stage(
    const float* __restrict__ in, size_t in_stride,
    float* __restrict__ out,
    const float* __restrict__ wm, const float* __restrict__ bias,
    const float* __restrict__ prev_s, const float* __restrict__ prev_q,
    const float* __restrict__ skip,
    float* __restrict__ stat_s, float* __restrict__ stat_q,
    Taps tp)
{
    __shared__ __align__(16) float s_w[16*9*16];   // [ci][k][co]
    __shared__ __align__(16) float s_in[16*360];   // [ci][r(10)][c(36, 34 used)]
    __shared__ float s_a[16], s_b[16];
    __shared__ float s_red[4][4][8];    // [warp][cg][4 s + 4 q]

    const int osl = blockIdx.y;
    const int tile = blockIdx.x;
    const int tz0 = (tile >> 2) << 3;   // 16 z-tiles of 8
    const int ty0 = (tile &  3) << 5;   // 4 y-tiles of 32
    const int tid = threadIdx.x;
    const int cg    = tid & 3;          // co-group: co = cg*4 .. cg*4+3
    const int slot  = tid >> 2;         // 0..31
    const int tz    = slot >> 2;        // 0..7
    const int strip = slot & 3;         // 0..3 -> y = strip*8 .. strip*8+7

    // inline finalize of previous stage's instance-norm stats
    if (MODE > 0 && tid < 16){
        double sd = (double)prev_s[tid];
        double qd = (double)prev_q[tid];
        double mean = sd / 2097152.0;
        double var  = qd / 2097152.0 - mean*mean;
        double isd  = 1.0 / sqrt(var + 1e-5);
        s_a[tid] = (float)isd;
        s_b[tid] = (float)(-mean*isd);
    }

    // tile-load slots over 340 logical entries (r=j/34, c=j%34):
    // slots 0,1 for all threads; slot 2 only for tid<84 (340-256).
    int pxs[3], sos[3]; bool oks[3];
#pragma unroll
    for (int s3=0; s3<3; s3++){
        int j = tid + s3*128;
        int r = j/34, c = j - r*34;
        int gz = tz0 + r - 1, gy = ty0 + c - 1;
        oks[s3] = (j < 340) && ((unsigned)gz < 128u) && ((unsigned)gy < 128u);
        pxs[s3] = gz*128 + gy;
        sos[s3] = r*36 + c;
    }
    const bool has2 = tid < 84;

    ull acc[2][8];                      // [co-pair][py]
#pragma unroll
    for (int p=0;p<2;p++)
#pragma unroll
    for (int py=0;py<8;py++) acc[p][py] = 0ull;

    for (int e=0; e<3; e++){
        const int isl = tp.isl[osl][e];
        if (isl < 0) continue;
        __syncthreads();
        // weights: coalesced copy of pre-merged slab (576 float4)
        {
            const float4* wmp = reinterpret_cast<const float4*>(wm + (osl*3 + e)*2304);
            float4* swp = reinterpret_cast<float4*>(s_w);
#pragma unroll
            for (int it=0; it<4; it++)
                swp[tid + it*128] = wmp[tid + it*128];
            if (tid < 64) swp[tid + 512] = wmp[tid + 512];
        }
        // input tile: ci batched in groups of 4, 3 slots per thread
        const float* ip = in + (size_t)isl*in_stride;
#pragma unroll
        for (int s3=0; s3<3; s3++){
            if (s3==2 && !has2) break;
            const bool ok = oks[s3];
            const int px = pxs[s3], so = sos[s3];
#pragma unroll
            for (int cgl=0; cgl<16; cgl+=4){
                float xv[4];
#pragma unroll
                for (int u2=0; u2<4; u2++)
                    xv[u2] = ok ? ip[(cgl+u2)*HW + px] : 0.f;
                if (MODE == 2){
                    float svv[4];
#pragma unroll
                    for (int u2=0; u2<4; u2++)
                        svv[u2] = ok ? skip[(cgl+u2)*HW + px] : 0.f;
#pragma unroll
                    for (int u2=0; u2<4; u2++){
                        float t = fmaxf(fmaf(xv[u2], s_a[cgl+u2], s_b[cgl+u2]) + svv[u2], 0.f);
                        s_in[(cgl+u2)*360 + so] = ok ? t : 0.f;
                    }
                } else if (MODE == 1){
#pragma unroll
                    for (int u2=0; u2<4; u2++){
                        float t = fmaxf(fmaf(xv[u2], s_a[cgl+u2], s_b[cgl+u2]), 0.f);
                        s_in[(cgl+u2)*360 + so] = ok ? t : 0.f;
                    }
                } else {
#pragma unroll
                    for (int u2=0; u2<4; u2++)
                        s_in[(cgl+u2)*360 + so] = xv[u2];
                }
            }
        }
        __syncthreads();

        // compute: 8 px x 4 co, software-pipelined (ci,kz) rows.
        const float* sbase = s_in + tz*36 + strip*8;
        const float* row   = sbase;               // (ci=0,kz=0)
        const float* wptr  = s_w + cg*4;          // advances +48 floats/row
        float4 vA = *reinterpret_cast<const float4*>(row);
        float4 vB = *reinterpret_cast<const float4*>(row + 4);
        float2 vC = *reinterpret_cast<const float2*>(row + 8);
        ulonglong2 w0 = *reinterpret_cast<const ulonglong2*>(wptr);
        ulonglong2 w1 = *reinterpret_cast<const ulonglong2*>(wptr + 16);
        ulonglong2 w2 = *reinterpret_cast<const ulonglong2*>(wptr + 32);
#pragma unroll 1
        for (int ci=0; ci<16; ci++){
#pragma unroll
            for (int kz=0; kz<3; kz++){
                // prefetch next row + next weight trio (clamped on last iter)
                const bool last = (kz==2) && (ci==15);
                const float* nrow = last ? row : (row + ((kz<2) ? 36 : (360-72)));
                const float* nw   = last ? wptr : (wptr + 48);
                float4 nA = *reinterpret_cast<const float4*>(nrow);
                float4 nB = *reinterpret_cast<const float4*>(nrow + 4);
                float2 nC = *reinterpret_cast<const float2*>(nrow + 8);
                ulonglong2 m0 = *reinterpret_cast<const ulonglong2*>(nw);
                ulonglong2 m1 = *reinterpret_cast<const ulonglong2*>(nw + 16);
                ulonglong2 m2 = *reinterpret_cast<const ulonglong2*>(nw + 32);

                ull pv[10];
                pv[0]=pack2(vA.x); pv[1]=pack2(vA.y); pv[2]=pack2(vA.z); pv[3]=pack2(vA.w);
                pv[4]=pack2(vB.x); pv[5]=pack2(vB.y); pv[6]=pack2(vB.z); pv[7]=pack2(vB.w);
                pv[8]=pack2(vC.x); pv[9]=pack2(vC.y);
#pragma unroll
                for (int py=0; py<8; py++){
                    fma2(acc[0][py], pv[py],   w0.x);
                    fma2(acc[1][py], pv[py],   w0.y);
                }
#pragma unroll
                for (int py=0; py<8; py++){
                    fma2(acc[0][py], pv[py+1], w1.x);
                    fma2(acc[1][py], pv[py+1], w1.y);
                }
#pragma unroll
                for (int py=0; py<8; py++){
                    fma2(acc[0][py], pv[py+2], w2.x);
                    fma2(acc[1][py], pv[py+2], w2.y);
                }
                vA = nA; vB = nB; vC = nC;
                w0 = m0; w1 = m1; w2 = m2;
                row = nrow; wptr = nw;
            }
        }
    }

    // epilogue: bias, vectorized store, fused stats
    const int oz  = tz0 + tz;
    const int oy0 = ty0 + strip*8;
    float* op = out + (size_t)osl*CHW + oz*128 + oy0;

    float sv[4], qv[4];
#pragma unroll
    for (int p=0; p<2; p++){
        const int c0 = cg*4 + 2*p, c1 = c0 + 1;
        const float b0 = bias[c0], b1 = bias[c1];
        float r0[8], r1[8];
#pragma unroll
        for (int py=0; py<8; py++){
            float x,y; unpack2(acc[p][py], x, y);
            r0[py] = x + b0;
            r1[py] = y + b1;
        }
        *reinterpret_cast<float4*>(op + c0*HW)     = make_float4(r0[0],r0[1],r0[2],r0[3]);
        *reinterpret_cast<float4*>(op + c0*HW + 4) = make_float4(r0[4],r0[5],r0[6],r0[7]);
        *reinterpret_cast<float4*>(op + c1*HW)     = make_float4(r1[0],r1[1],r1[2],r1[3]);
        *reinterpret_cast<float4*>(op + c1*HW + 4) = make_float4(r1[4],r1[5],r1[6],r1[7]);
        float s0=0.f,q0=0.f,s1=0.f,q1=0.f;
#pragma unroll
        for (int py=0; py<8; py++){
            s0 += r0[py]; q0 += r0[py]*r0[py];
            s1 += r1[py]; q1 += r1[py]*r1[py];
        }
        sv[2*p]=s0; qv[2*p]=q0; sv[2*p+1]=s1; qv[2*p+1]=q1;
    }
    // reduce over the 8 slots in this warp (lane bits 2..4)
#pragma unroll
    for (int o=16; o>=4; o>>=1){
#pragma unroll
        for (int j=0;j<4;j++){
            sv[j] += __shfl_xor_sync(0xffffffffu, sv[j], o);
            qv[j] += __shfl_xor_sync(0xffffffffu, qv[j], o);
        }
    }
    if ((tid & 31) < 4){
        const int wd = tid >> 5;
#pragma unroll
        for (int j=0;j<4;j++){
            s_red[wd][cg][j]   = sv[j];
            s_red[wd][cg][4+j] = qv[j];
        }
    }
    __syncthreads();
    if (tid < 32){
        const bool isq = tid >= 16;
        const int co = tid & 15;
        const int cgg = co >> 2, j = co & 3;
        const int off = isq ? (4+j) : j;
        float t = s_red[0][cgg][off] + s_red[1][cgg][off]
                + s_red[2][cgg][off] + s_red[3][cgg][off];
        t *= tp.mult[osl];
        atomicAdd(isq ? &stat_q[co] : &stat_s[co], t);
    }
}

// ---------------- fused final elementwise + forward projection ----------------
// final[sl] = relu( norm3(s3[sl]) + relu( norm1(s2[skm[sl]]) + V ) )
// out[c,0,z,u] = weighted slice sum at (z,y=u)
// out[c,1,z,u] = column sum over y of slice sel(u); u==0 sums only y=0..63
//   (reference fp32: x=+-3.9e-15 at uu=0, valid mask kills y in [64,127]).
__global__ __launch_bounds__(128) void forward_proj(
    const float* __restrict__ s3, const float* __restrict__ s2,
    const float* __restrict__ V, float* __restrict__ out)
{
    __shared__ float red[9][4];
    __shared__ float rs[9];
    const int c = blockIdx.x >> 7, z = blockIdx.x & 127;
    const int u = threadIdx.x;
    const int   skm[9]  = {0,1,2,2,2,2,2,3,4};
    const float mult[9] = {1.f,1.f,1.f,1.f,120.f,1.f,1.f,1.f,1.f};

    // inline stats finalize: bank1 (A2 output) and bank3 (B2 output)
    double sd1 = (double)g_sum[16+c], qd1 = (double)g_sumsq[16+c];
    double me1 = sd1/2097152.0;
    double i1d = 1.0/sqrt(qd1/2097152.0 - me1*me1 + 1e-5);
    const float i1 = (float)i1d, b1c = (float)(-me1*i1d);
    double sd3 = (double)g_sum[48+c], qd3 = (double)g_sumsq[48+c];
    double me3 = sd3/2097152.0;
    double i3d = 1.0/sqrt(qd3/2097152.0 - me3*me3 + 1e-5);
    const float i3 = (float)i3d, b3c = (float)(-me3*i3d);

    const int pix = z*128 + u;
    const float vb = V[c*HW + pix];

    float vals[9]; float s0 = 0.f;
#pragma unroll
    for (int sdx=0; sdx<9; sdx++){
        float t2 = s2[(size_t)(skm[sdx]*16 + c)*HW + pix];
        float sk = fmaxf(fmaf(t2, i1, b1c) + vb, 0.f);
        float t3 = s3[(size_t)(sdx*16 + c)*HW + pix];
        float fv = fmaxf(fmaf(t3, i3, b3c) + sk, 0.f);
        vals[sdx] = fv;
        s0 += mult[sdx]*fv;
    }
    out[(c*2+0)*HW + pix] = s0;

    const int lane = u & 31, wid = u >> 5;
#pragma unroll
    for (int sdx=0; sdx<9; sdx++){
        float v = vals[sdx];
#pragma unroll
        for (int o=16;o>0;o>>=1) v += __shfl_xor_sync(0xffffffffu, v, o);
        if (lane==0) red[sdx][wid]=v;
    }
    __syncthreads();
    if (u < 9) rs[u] = red[u][0]+red[u][1]+red[u][2]+red[u][3];
    __syncthreads();
    const int sl = (u<4) ? u : (u>123 ? u-119 : 4);
    float o1 = (u==0) ? (red[0][0]+red[0][1]) : rs[sl];
    out[(c*2+1)*HW + pix] = o1;
}

// ---------------- launch ----------------
extern "C" void kernel_launch(void* const* d_in, const int* in_sizes, int n_in,
                              void* d_out, int out_size)
{
    (void)in_sizes; (void)n_in; (void)out_size;
    const float* V    = (const float*)d_in[0];
    const float* w_a1 = (const float*)d_in[1];
    const float* b_a1 = (const float*)d_in[2];
    const float* w_a2 = (const float*)d_in[3];
    const float* b_a2 = (const float*)d_in[4];
    const float* w_b1 = (const float*)d_in[5];
    const float* b_b1 = (const float*)d_in[6];
    const float* w_b2 = (const float*)d_in[7];
    const float* b_b2 = (const float*)d_in[8];
    float* out = (float*)d_out;

    float *b1,*b2,*b3,*gsum,*gsq,*gwm;
    cudaGetSymbolAddress((void**)&b1,    g_b1);
    cudaGetSymbolAddress((void**)&b2,    g_b2);
    cudaGetSymbolAddress((void**)&b3,    g_b3);
    cudaGetSymbolAddress((void**)&gsum,  g_sum);
    cudaGetSymbolAddress((void**)&gsq,   g_sumsq);
    cudaGetSymbolAddress((void**)&gwm,   g_wm);

    // merged tap tables: (input slice, kx bitmask) per output slice
    Taps tA1 = {
        { {0,-1,-1},{0,-1,-1},{0,-1,-1} },
        { {6,0,0},{7,0,0},{3,0,0} },
        { 1.f,126.f,1.f }
    };
    Taps tA2 = {
        { {0,1,-1},{0,1,-1},{1,-1,-1},{1,2,-1},{1,2,-1} },
        { {2,4,0},{1,6,0},{7,0,0},{3,4,0},{1,2,0} },
        { 1.f,1.f,124.f,1.f,1.f }
    };
    Taps tB1 = {
        { {0,1,-1},{0,1,2},{1,2,-1},{2,-1,-1},{2,3,-1},{2,3,4},{3,4,-1} },
        { {2,4,0},{1,2,4},{1,6,0},{7,0,0},{3,4,0},{1,2,4},{1,2,0} },
        { 1.f,1.f,1.f,122.f,1.f,1.f,1.f }
    };
    Taps tB2 = {
        { {0,1,-1},{0,1,2},{1,2,3},{2,3,-1},{3,-1,-1},{3,4,-1},{3,4,5},{4,5,6},{5,6,-1} },
        { {2,4,0},{1,2,4},{1,2,4},{1,6,0},{7,0,0},{3,4,0},{1,2,4},{1,2,4},{1,2,0} },
        { 1.f,1.f,1.f,1.f,120.f,1.f,1.f,1.f,1.f }
    };

    MergeArgs ma;
    ma.w[0]=w_a1; ma.w[1]=w_a2; ma.w[2]=w_b1; ma.w[3]=w_b2;
    ma.tp[0]=tA1; ma.tp[1]=tA2; ma.tp[2]=tB1; ma.tp[3]=tB2;
    ma.n_osl[0]=3; ma.n_osl[1]=5; ma.n_osl[2]=7; ma.n_osl[3]=9;

    // setup: merge weights for all 4 stages + zero stats
    merge_weights<<<dim3(3,9,4),128>>>(ma);

    // A1: raw V (slice stride 0) -> b1 (3 slices), stats bank 0
    conv_stage<0><<<dim3(64,3),128>>>(V, 0, b1, gwm+0*WSTG, b_a1,
                                      nullptr, nullptr, nullptr,
                                      gsum+0, gsq+0, tA1);

    // A2: norm_relu(b1, bank0) -> b2 (5), stats bank 1
    conv_stage<1><<<dim3(64,5),128>>>(b1, CHW, b2, gwm+1*WSTG, b_a2,
                                      gsum+0, gsq+0, nullptr,
                                      gsum+16, gsq+16, tA2);

    // B1: relu(norm(b2, bank1) + V) -> b1 (7), stats bank 2
    conv_stage<2><<<dim3(64,7),128>>>(b2, CHW, b1, gwm+2*WSTG, b_b1,
                                      gsum+16, gsq+16, V,
                                      gsum+32, gsq+32, tB1);

    // B2: norm_relu(b1, bank2) -> b3 (9), stats bank 3
    conv_stage<1><<<dim3(64,9),128>>>(b1, CHW, b3, gwm+3*WSTG, b_b2,
                                      gsum+32, gsq+32, nullptr,
                                      gsum+48, gsq+48, tB2);

    // fused final norm+skip+relu + both projections (bank1+bank3 inline)
    forward_proj<<<16*128,128>>>(b3, b2, V, out);
}